// round 4
// baseline (speedup 1.0000x reference)
#include <cuda_runtime.h>
#include <cstdint>

// Soft-DTW (gamma=1), 64 batches of 1024x1024.
// Barrier-free warp-pipelined wavefront:
//   - 2 plain CTAs per batch (rank = blockIdx.x&1): rows 0..511 / 512..1023
//   - 256 threads/CTA = 8 warps, 2 rows per thread (rows 2l, 2l+1 of warp chunk)
//   - intra-warp neighbor via __shfl_up_sync
//   - inter-warp boundary via tagged 64-bit smem ring (value<<32 | (y+1)),
//     single volatile 8B store/load, depth 256 with progress-based throttle
//   - inter-CTA boundary via tagged 64-bit global ring + depth-3 reg prefetch
// Log2-domain: coords pre-scaled by sqrt(log2 e); softmin = mn - lg2(1+2^(mn-mid)+2^(mn-mx))
// Invalid cells get huge-but-finite values via sentinel contour padding (no inf/NaN).

#define NBATCH 64
#define NPTS   1024
#define NDIAG  2047
#define HALF   512
#define TPB    256
#define NW     8
#define RINGD  256
#define BIGV   1.0e30f
#define SENT   1.0e17f

__device__ float g_partial[NBATCH];
__device__ unsigned long long gring[NBATCH][2048];

__device__ __forceinline__ float ex2f(float x) {
    float r; asm("ex2.approx.ftz.f32 %0, %1;" : "=f"(r) : "f"(x)); return r;
}
__device__ __forceinline__ float lg2f(float x) {
    float r; asm("lg2.approx.ftz.f32 %0, %1;" : "=f"(r) : "f"(x)); return r;
}
__device__ __forceinline__ uint32_t smem_u32(const void* p) {
    uint32_t a;
    asm("{ .reg .u64 t; cvta.to.shared.u64 t, %1; cvt.u32.u64 %0, t; }"
        : "=r"(a) : "l"(p));
    return a;
}

// softmin in log2 domain: one exp arg is always 0 -> 2 ex2 + 1 lg2.
__device__ __forceinline__ float cellv(float dg2, float up1, float lf1, float Dl) {
    float t1  = fminf(dg2, up1);
    float t2  = fmaxf(dg2, up1);
    float mn  = fminf(t1, lf1);
    float mx  = fmaxf(t2, lf1);
    float mid = fminf(t2, fmaxf(t1, lf1));
    float s   = 1.0f + ex2f(mn - mid) + ex2f(mn - mx);
    return Dl + (mn - lg2f(s));
}

__global__ __launch_bounds__(TPB, 1)
void dtw_kernel(const float* __restrict__ snake, const float* __restrict__ contour)
{
    __shared__ float2 scp[NPTS + 2];                 // padded scaled contour
    __shared__ unsigned long long ring_s[NW - 1][RINGD];
    __shared__ int prog[NW];

    const int tid  = threadIdx.x;
    const int lane = tid & 31;
    const int wid  = tid >> 5;
    const int rank = blockIdx.x & 1;
    const int b    = blockIdx.x >> 1;
    const float SCALE = 1.2011224087864498f;         // sqrt(log2 e)

    // Zero rings/progress (smem is garbage at launch).
    for (int k = tid; k < (NW - 1) * RINGD; k += TPB)
        ((unsigned long long*)ring_s)[k] = 0ULL;
    if (tid < NW) prog[tid] = 0;

    // Scaled contour + sentinel pads.
    for (int k = tid; k < NPTS; k += TPB) {
        float2 c = ((const float2*)contour)[b * NPTS + k];
        scp[1 + k] = make_float2(c.x * SCALE, c.y * SCALE);
    }
    if (tid == 0) { scp[0] = make_float2(SENT, SENT); scp[NPTS + 1] = make_float2(SENT, SENT); }

    // This thread's two snake rows (row_a even -> one float4 load).
    const int row_a = rank * HALF + wid * 64 + 2 * lane;
    float4 s4 = ((const float4*)snake)[(b * NPTS + row_a) >> 1];
    const float sax = s4.x * SCALE, say = s4.y * SCALE;
    const float sbx = s4.z * SCALE, sby = s4.w * SCALE;

    __syncthreads();   // the only CTA barrier

    float cur_a = BIGV, cur_b = BIGV, cur_a_old = BIGV, nb2 = BIGV;
    if (rank == 0 && tid == 0) nb2 = 0.0f;   // R(-1,-1)=0 unity for cell (0,0)

    unsigned long long pf0 = 0, pf1 = 0, pf2 = 0;   // global-ring prefetch regs
    int jp = 1 - row_a;                              // j_a + 1 at diagonal y
    const int  yEnd  = rank ? (NDIAG - 1) : 1535;    // rank0: last diag touching rows<=511
    const bool gprod = (rank == 0 && wid == NW - 1 && lane == 31);
    const bool gcons = (rank == 1 && wid == 0 && lane == 0);

    for (int y = 0; y <= yEnd; ++y, ++jp) {
        // Up-neighbor (row_a - 1) value at diag y-1.
        float nb1 = __shfl_up_sync(0xFFFFFFFFu, cur_b, 1);
        if (lane == 0) {
            if (wid == 0) {
                nb1 = BIGV;
                if (gcons) {
                    if (y >= HALF && y <= 1535) {   // only these entries feed valid cells
                        unsigned long long p = pf0;
                        if ((unsigned)p != (unsigned)y) {
                            const unsigned long long* ap = &gring[b][y - 1];
                            do {
                                asm volatile("ld.global.cg.u64 %0, [%1];" : "=l"(p) : "l"(ap));
                            } while ((unsigned)p != (unsigned)y);
                        }
                        nb1 = __uint_as_float((unsigned)(p >> 32));
                    }
                    // rotate + prefetch entry y+2 (used at step y+3)
                    pf0 = pf1; pf1 = pf2;
                    const unsigned long long* ap2 = &gring[b][min(y + 2, 2046)];
                    asm volatile("ld.global.cg.u64 %0, [%1];" : "=l"(pf2) : "l"(ap2));
                }
            } else if (y >= 1) {
                unsigned long long p;
                uint32_t addr = smem_u32(&ring_s[wid - 1][(y - 1) & (RINGD - 1)]);
                do {
                    asm volatile("ld.volatile.shared.u64 %0, [%1];" : "=l"(p) : "r"(addr));
                } while ((unsigned)p != (unsigned)y);
                nb1 = __uint_as_float((unsigned)(p >> 32));
                if ((y & 63) == 0) ((volatile int*)prog)[wid] = y;  // consumption progress
            }
        }

        // Distances (sentinel pads make out-of-range huge; no masks).
        int jca = min(max(jp,     0), NPTS + 1);
        int jcb = min(max(jp - 1, 0), NPTS + 1);
        float2 ca = scp[jca], cb = scp[jcb];
        float dax = sax - ca.x, day = say - ca.y;
        float Dla = fmaf(day, day, dax * dax);
        float dbx = sbx - cb.x, dby = sby - cb.y;
        float Dlb = fmaf(dby, dby, dbx * dbx);

        // Two cells on this anti-diagonal (independent).
        float new_a = cellv(nb2,       nb1,   cur_a, Dla);
        float new_b = cellv(cur_a_old, cur_a, cur_b, Dlb);

        // Publish boundary row (row_a+1 of lane 31 = warp's bottom row).
        if (lane == 31) {
            unsigned long long p =
                ((unsigned long long)__float_as_uint(new_b) << 32) | (unsigned)(y + 1);
            if (wid < NW - 1) {
                if ((y & 63) == 0) {          // throttle: keep <=~192 entries ahead
                    volatile int* pr = (volatile int*)&prog[wid + 1];
                    while (*pr < y - 192) { }
                }
                uint32_t addr = smem_u32(&ring_s[wid][y & (RINGD - 1)]);
                asm volatile("st.volatile.shared.u64 [%0], %1;" :: "r"(addr), "l"(p) : "memory");
            } else if (gprod) {
                unsigned long long* ap = &gring[b][y];
                asm volatile("st.global.cg.u64 [%0], %1;" :: "l"(ap), "l"(p) : "memory");
            }
        }

        // Rotate state.
        nb2 = nb1; cur_a_old = cur_a; cur_a = new_a; cur_b = new_b;
    }

    if (rank == 1 && wid == NW - 1 && lane == 31)
        g_partial[b] = cur_b * 0.69314718055994531f;   // log2 -> ln
}

__global__ void reduce_kernel(float* __restrict__ out)
{
    float v = g_partial[threadIdx.x] + g_partial[threadIdx.x + 32];
    #pragma unroll
    for (int off = 16; off > 0; off >>= 1)
        v += __shfl_down_sync(0xFFFFFFFFu, v, off);
    if (threadIdx.x == 0)
        out[0] = v * (1.0f / NBATCH);
}

extern "C" void kernel_launch(void* const* d_in, const int* in_sizes, int n_in,
                              void* d_out, int out_size)
{
    const float* snake   = (const float*)d_in[0];
    const float* contour = (const float*)d_in[1];
    float* out = (float*)d_out;

    dtw_kernel<<<NBATCH * 2, TPB>>>(snake, contour);
    reduce_kernel<<<1, 32>>>(out);
}

// round 5
// speedup vs baseline: 3.3914x; 3.3914x over previous
#include <cuda_runtime.h>
#include <cstdint>

// Soft-DTW (gamma=1), 64 batches of 1024x1024, one CTA per batch.
// 512 threads, 2 rows per thread (rows 2t, 2t+1), anti-diagonal wavefront,
// one __syncthreads per diagonal. Triangular warp-skip: each warp only runs
// its active window [64w, 64w+1086] (contiguous), idling through bare
// barriers outside it (all threads execute exactly NDIAG barriers).
// Log2-domain: coords pre-scaled by sqrt(log2 e); softmin needs 2 ex2 + 1 lg2.
// Invalid cells get huge-but-finite values via sentinel contour padding.

#define NBATCH 64
#define NPTS   1024
#define NDIAG  2047
#define TPB    512
#define NWARP  16
#define BIGV   1.0e30f
#define SENT   1.0e17f

__device__ float g_partial[NBATCH];

__device__ __forceinline__ float ex2f(float x) {
    float r; asm("ex2.approx.ftz.f32 %0, %1;" : "=f"(r) : "f"(x)); return r;
}
__device__ __forceinline__ float lg2f(float x) {
    float r; asm("lg2.approx.ftz.f32 %0, %1;" : "=f"(r) : "f"(x)); return r;
}

// softmin in log2 domain: one exp arg is always 0 -> 2 ex2 + 1 lg2.
__device__ __forceinline__ float cellv(float a, float bq, float c, float Dl) {
    float t1  = fminf(a, bq);
    float t2  = fmaxf(a, bq);
    float mn  = fminf(t1, c);
    float mx  = fmaxf(t2, c);
    float mid = fminf(t2, fmaxf(t1, c));
    float s   = 1.0f + (ex2f(mn - mid) + ex2f(mn - mx));
    return Dl + (mn - lg2f(s));
}

__global__ __launch_bounds__(TPB, 1)
void dtw_kernel(const float* __restrict__ snake, const float* __restrict__ contour)
{
    __shared__ float2 scp[NPTS + 2];     // padded scaled contour
    __shared__ float  bufb[2][NWARP];    // per-warp bottom-row value, ping-pong

    const int tid  = threadIdx.x;
    const int lane = tid & 31;
    const int wid  = tid >> 5;
    const int b    = blockIdx.x;
    const float SCALE = 1.2011224087864498f;   // sqrt(log2 e)

    // Scaled contour + sentinel pads.
    for (int k = tid; k < NPTS; k += TPB) {
        float2 c = ((const float2*)contour)[b * NPTS + k];
        scp[1 + k] = make_float2(c.x * SCALE, c.y * SCALE);
    }
    if (tid == 0) { scp[0] = make_float2(SENT, SENT); scp[NPTS + 1] = make_float2(SENT, SENT); }
    if (tid < 2 * NWARP) ((float*)bufb)[tid] = BIGV;

    // This thread's two snake rows (one float4 load).
    const int row_a = 2 * tid;
    float4 s4 = ((const float4*)snake)[b * TPB + tid];
    const float sax = s4.x * SCALE, say = s4.y * SCALE;
    const float sbx = s4.z * SCALE, sby = s4.w * SCALE;

    __syncthreads();

    // State: cur_a/cur_b = R[row_a/row_b, j-1]; cur_a_old = cur_a two diags ago;
    // nb2 = up-neighbor (row_a-1) two diags ago.
    float cur_a = BIGV, cur_b = BIGV, cur_a_old = BIGV, nb2 = BIGV;
    if (tid == 0) nb2 = 0.0f;          // R(-1,-1)=0 => cell(0,0) = D(0,0)

    const int yLo   = wid << 6;                       // 64*wid
    const int yStop = min(yLo + 1086, NDIAG - 1);

    int y = 0;
    // Pre-window: bare barriers.
    for (; y < yLo; ++y) __syncthreads();

    int jp = y - row_a + 1;            // j_a + 1
    // Active window.
    for (; y <= yStop; ++y, ++jp) {
        // Up-neighbor (row_a-1) at diag y-1: shfl within warp, smem across warps.
        float nb1 = __shfl_up_sync(0xFFFFFFFFu, cur_b, 1);
        if (lane == 0) nb1 = (wid == 0) ? BIGV : bufb[(y - 1) & 1][wid - 1];

        // Distances (sentinel pads make out-of-range huge; no masks).
        int jca = min(max(jp,     0), NPTS + 1);
        int jcb = min(max(jp - 1, 0), NPTS + 1);
        float2 ca = scp[jca], cb = scp[jcb];
        float dax = sax - ca.x, day = say - ca.y;
        float Dla = fmaf(day, day, dax * dax);
        float dbx = sbx - cb.x, dby = sby - cb.y;
        float Dlb = fmaf(dby, dby, dbx * dbx);

        // Two cells on this anti-diagonal (independent of each other).
        float new_a = cellv(nb2,       nb1,   cur_a, Dla);
        float new_b = cellv(cur_a_old, cur_a, cur_b, Dlb);

        if (lane == 31) bufb[y & 1][wid] = new_b;

        nb2 = nb1; cur_a_old = cur_a; cur_a = new_a; cur_b = new_b;
        __syncthreads();
    }
    // Post-window: bare barriers.
    for (; y < NDIAG; ++y) __syncthreads();

    if (tid == TPB - 1)
        g_partial[b] = cur_b * 0.69314718055994531f;   // log2 -> ln
}

__global__ void reduce_kernel(float* __restrict__ out)
{
    float v = g_partial[threadIdx.x] + g_partial[threadIdx.x + 32];
    #pragma unroll
    for (int off = 16; off > 0; off >>= 1)
        v += __shfl_down_sync(0xFFFFFFFFu, v, off);
    if (threadIdx.x == 0)
        out[0] = v * (1.0f / NBATCH);
}

extern "C" void kernel_launch(void* const* d_in, const int* in_sizes, int n_in,
                              void* d_out, int out_size)
{
    const float* snake   = (const float*)d_in[0];
    const float* contour = (const float*)d_in[1];
    float* out = (float*)d_out;

    dtw_kernel<<<NBATCH, TPB>>>(snake, contour);
    reduce_kernel<<<1, 32>>>(out);
}

// round 6
// speedup vs baseline: 3.9688x; 1.1703x over previous
#include <cuda_runtime.h>
#include <cstdint>

// Soft-DTW (gamma=1), 64 batches of 1024x1024, one CTA per batch.
// Warp-skewed block pipeline: diagonals grouped in blocks of K=16.
// Warp w (rows 64w..64w+63, 2 rows/thread) computes block t at superstep
// s = t + w. Inter-warp boundary values flow through a double-buffered smem
// strip written one superstep ahead of consumption -> ONE __syncthreads per
// superstep (143 total) instead of one per diagonal (2047).
// Triangular skip: warp w only processes blocks [4w, min(127,4w+67)].
// Log2-domain: coords pre-scaled by sqrt(log2 e); softmin = 2 ex2 + 1 lg2.
// Invalid cells carry huge-but-finite values via sentinel contour padding.

#define NBATCH 64
#define NPTS   1024
#define NDIAG  2047
#define TPB    512
#define NW     16
#define KB     16
#define NBLK   128          // ceil(NDIAG / KB)
#define NSUP   (NBLK + NW - 1)
#define BIGV   1.0e30f
#define SENT   1.0e17f

__device__ float g_partial[NBATCH];

__device__ __forceinline__ float ex2f(float x) {
    float r; asm("ex2.approx.ftz.f32 %0, %1;" : "=f"(r) : "f"(x)); return r;
}
__device__ __forceinline__ float lg2f(float x) {
    float r; asm("lg2.approx.ftz.f32 %0, %1;" : "=f"(r) : "f"(x)); return r;
}

// softmin in log2 domain: one exp arg is always 0 -> 2 ex2 + 1 lg2.
__device__ __forceinline__ float cellv(float a, float bq, float c, float Dl) {
    float t1  = fminf(a, bq);
    float t2  = fmaxf(a, bq);
    float mn  = fminf(t1, c);
    float mx  = fmaxf(t2, c);
    float mid = fminf(t2, fmaxf(t1, c));
    float s   = 1.0f + (ex2f(mn - mid) + ex2f(mn - mx));
    return Dl + (mn - lg2f(s));
}

__global__ __launch_bounds__(TPB, 1)
void dtw_kernel(const float* __restrict__ snake, const float* __restrict__ contour)
{
    __shared__ float2 scp[NPTS + 2];            // padded scaled contour
    __shared__ float  bufk[2][NW][KB + 1];      // boundary strip, double-buffered
                                                // [slot][warp][k]: k=0 -> diag tK-1,
                                                // k>=1 -> diag tK+k-1

    const int tid  = threadIdx.x;
    const int lane = tid & 31;
    const int wid  = tid >> 5;
    const int b    = blockIdx.x;
    const float SCALE = 1.2011224087864498f;    // sqrt(log2 e)

    for (int k = tid; k < NPTS; k += TPB) {
        float2 c = ((const float2*)contour)[b * NPTS + k];
        scp[1 + k] = make_float2(c.x * SCALE, c.y * SCALE);
    }
    if (tid == 0) { scp[0] = make_float2(SENT, SENT); scp[NPTS + 1] = make_float2(SENT, SENT); }
    for (int k = tid; k < 2 * NW * (KB + 1); k += TPB)
        ((float*)bufk)[k] = BIGV;

    const int row_a = 2 * tid;                  // rows row_a, row_a+1
    float4 s4 = ((const float4*)snake)[b * TPB + tid];
    const float sax = s4.x * SCALE, say = s4.y * SCALE;
    const float sbx = s4.z * SCALE, sby = s4.w * SCALE;

    __syncthreads();

    float cur_a = BIGV, cur_b = BIGV, cur_a_old = BIGV, nb2 = BIGV;
    if (tid == 0) nb2 = 0.0f;                   // R(-1,-1)=0 => cell(0,0)=D(0,0)

    const int tLo = 4 * wid;
    const int tHi = min(NBLK - 1, 4 * wid + 67);

    // Rolling contour regs: cb_roll = scp[clamp(jp-1)] entering each iteration.
    int jp = tLo * KB - row_a + 1;              // j_a + 1 at first active diag
    float2 cb_roll = scp[min(max(jp - 1, 0), NPTS + 1)];

    for (int s = 0; s < NSUP; ++s) {
        const int t = s - wid;
        if (t >= tLo && t <= tHi) {
            const int yrem = NDIAG - t * KB;    // <KB only for the last block
            if (lane == 31) bufk[t & 1][wid][0] = cur_b;   // carry: diag tK-1
            #pragma unroll
            for (int k = 0; k < KB; ++k) {
                if (k >= yrem) break;
                // up-neighbor (row_a-1) at diag y-1
                float nb1 = __shfl_up_sync(0xFFFFFFFFu, cur_b, 1);
                if (lane == 0)
                    nb1 = (wid == 0) ? BIGV : bufk[t & 1][wid - 1][k];

                int jc = min(max(jp, 0), NPTS + 1);
                float2 cnew = scp[jc];
                float dax = sax - cnew.x,    day = say - cnew.y;
                float Dla = fmaf(day, day, dax * dax);
                float dbx = sbx - cb_roll.x, dby = sby - cb_roll.y;
                float Dlb = fmaf(dby, dby, dbx * dbx);

                float new_a = cellv(nb2,       nb1,   cur_a, Dla);
                float new_b = cellv(cur_a_old, cur_a, cur_b, Dlb);

                if (lane == 31) bufk[t & 1][wid][k + 1] = new_b;

                nb2 = nb1; cur_a_old = cur_a; cur_a = new_a; cur_b = new_b;
                cb_roll = cnew;
                ++jp;
            }
        }
        __syncthreads();
    }

    if (tid == TPB - 1)
        g_partial[b] = cur_b * 0.69314718055994531f;   // log2 -> ln (y=2046 value)
}

__global__ void reduce_kernel(float* __restrict__ out)
{
    float v = g_partial[threadIdx.x] + g_partial[threadIdx.x + 32];
    #pragma unroll
    for (int off = 16; off > 0; off >>= 1)
        v += __shfl_down_sync(0xFFFFFFFFu, v, off);
    if (threadIdx.x == 0)
        out[0] = v * (1.0f / NBATCH);
}

extern "C" void kernel_launch(void* const* d_in, const int* in_sizes, int n_in,
                              void* d_out, int out_size)
{
    const float* snake   = (const float*)d_in[0];
    const float* contour = (const float*)d_in[1];
    float* out = (float*)d_out;

    dtw_kernel<<<NBATCH, TPB>>>(snake, contour);
    reduce_kernel<<<1, 32>>>(out);
}

// round 12
// speedup vs baseline: 4.3397x; 1.0935x over previous
#include <cuda_runtime.h>

// Soft-DTW (gamma=1), 64 batches of 1024x1024, one CTA per batch.
// R6 skeleton (proven): warp-skewed block pipeline, KB=16 diags/block,
// 16 warps, 2 rows/thread, one __syncthreads per superstep (143 total),
// triangular block skip, log2-domain softmin (2 ex2 + 1 lg2 per cell).
// R12 changes (iso-semantics, fewer issue slots):
//  - extended sentinel padding: scp[jp+PAD] valid for every jp ever formed
//    (jp in [-62, 1088]) -> no per-iter clamps
//  - dot-form distance with per-point (cx, cy, cx^2+cy^2) in one LDS.128
//  - short final block (15 diags) via separate template instantiation,
//    no per-iter yrem check

#define NBATCH 64
#define NPTS   1024
#define TPB    512
#define NW     16
#define KB     16
#define NBLK   128                    // block 127 holds 15 diags (2032..2046)
#define NSUP   (NBLK + NW - 1)
#define BIGV   1.0e30f
#define SENT   1.0e17f
#define LN2F   0.69314718055994531f
#define PAD    64
#define SCPN   1160                   // indices used: [2, 1152]

__device__ float g_partial[NBATCH];

__device__ __forceinline__ float ex2f(float x) {
    float r; asm("ex2.approx.ftz.f32 %0, %1;" : "=f"(r) : "f"(x)); return r;
}
__device__ __forceinline__ float lg2f(float x) {
    float r; asm("lg2.approx.ftz.f32 %0, %1;" : "=f"(r) : "f"(x)); return r;
}

// softmin in log2 domain: one exp arg is always 0 -> 2 ex2 + 1 lg2.
__device__ __forceinline__ float cellv(float a, float bq, float c, float Dl) {
    float t1  = fminf(a, bq);
    float t2  = fmaxf(a, bq);
    float mn  = fminf(t1, c);
    float mx  = fmaxf(t2, c);
    float mid = fminf(t2, fmaxf(t1, c));
    float s   = 1.0f + (ex2f(mn - mid) + ex2f(mn - mx));
    return Dl + (mn - lg2f(s));
}

typedef float BufT[2][NW][KB + 1];

template<int KMAX>
__device__ __forceinline__ void run_block(
    BufT& bufk, int slot, int wid, int lane,
    const float4* pc, float4& cb,
    float& cur_a, float& cur_b, float& cur_a_old, float& nb2,
    float m2ax, float m2ay, float s2a,
    float m2bx, float m2by, float s2b)
{
    #pragma unroll
    for (int k = 0; k < KMAX; ++k) {
        float nb1 = __shfl_up_sync(0xFFFFFFFFu, cur_b, 1);
        if (lane == 0) nb1 = (wid == 0) ? BIGV : bufk[slot][wid - 1][k];

        float4 ca = pc[k];
        float Dla = fmaf(m2ay, ca.y, fmaf(m2ax, ca.x, s2a + ca.z));
        float Dlb = fmaf(m2by, cb.y, fmaf(m2bx, cb.x, s2b + cb.z));

        float new_a = cellv(nb2,       nb1,   cur_a, Dla);
        float new_b = cellv(cur_a_old, cur_a, cur_b, Dlb);

        if (lane == 31) bufk[slot][wid][k + 1] = new_b;

        nb2 = nb1; cur_a_old = cur_a; cur_a = new_a; cur_b = new_b;
        cb = ca;
    }
}

__global__ __launch_bounds__(TPB, 1)
void dtw_kernel(const float* __restrict__ snake, const float* __restrict__ contour)
{
    __shared__ float4 scp[SCPN];      // (cx, cy, cx^2+cy^2, 0), sentinel outside
    __shared__ BufT   bufk;           // boundary strip, double-buffered

    const int tid  = threadIdx.x;
    const int lane = tid & 31;
    const int wid  = tid >> 5;
    const int b    = blockIdx.x;
    const float SCALE = 1.2011224087864498f;   // sqrt(log2 e)

    // scp[idx] corresponds to jp = idx - PAD; valid contour at jp in [1,1024].
    for (int k = tid; k < SCPN; k += TPB) {
        int j = k - PAD;
        float cx = SENT, cy = SENT;
        if (j >= 1 && j <= NPTS) {
            float2 c = ((const float2*)contour)[b * NPTS + j - 1];
            cx = c.x * SCALE; cy = c.y * SCALE;
        }
        scp[k] = make_float4(cx, cy, fmaf(cx, cx, cy * cy), 0.f);
    }
    for (int k = tid; k < 2 * NW * (KB + 1); k += TPB)
        ((float*)bufk)[k] = BIGV;

    const int row_a = 2 * tid;                 // rows row_a, row_a+1
    float4 s4 = ((const float4*)snake)[b * TPB + tid];
    const float sax = s4.x * SCALE, say = s4.y * SCALE;
    const float sbx = s4.z * SCALE, sby = s4.w * SCALE;
    const float m2ax = -2.f * sax, m2ay = -2.f * say;
    const float s2a  = fmaf(sax, sax, say * say);
    const float m2bx = -2.f * sbx, m2by = -2.f * sby;
    const float s2b  = fmaf(sbx, sbx, sby * sby);

    __syncthreads();

    float cur_a = BIGV, cur_b = BIGV, cur_a_old = BIGV, nb2 = BIGV;
    if (tid == 0) nb2 = 0.0f;                  // R(-1,-1)=0 => cell(0,0)=D(0,0)

    const int tLo = 4 * wid;
    const int tHi = min(NBLK - 1, 4 * wid + 67);

    const int jp0 = tLo * KB - row_a + 1;      // jp at first active diag
    const float4* pc = &scp[jp0 + PAD];        // walks forward over blocks
    float4 cb = pc[-1];                        // scp[jp0 - 1 + PAD]

    for (int s = 0; s < NSUP; ++s) {
        const int t = s - wid;
        if (t >= tLo && t <= tHi) {
            const int slot = t & 1;
            if (lane == 31) bufk[slot][wid][0] = cur_b;   // carry: diag tKB-1
            if (t < NBLK - 1) {
                run_block<16>(bufk, slot, wid, lane, pc, cb,
                              cur_a, cur_b, cur_a_old, nb2,
                              m2ax, m2ay, s2a, m2bx, m2by, s2b);
                pc += 16;
            } else {
                run_block<15>(bufk, slot, wid, lane, pc, cb,
                              cur_a, cur_b, cur_a_old, nb2,
                              m2ax, m2ay, s2a, m2bx, m2by, s2b);
                pc += 15;
            }
        }
        __syncthreads();
    }

    if (tid == TPB - 1)
        g_partial[b] = cur_b * LN2F;           // log2 -> ln (value at diag 2046)
}

__global__ void reduce_kernel(float* __restrict__ out)
{
    float v = g_partial[threadIdx.x] + g_partial[threadIdx.x + 32];
    #pragma unroll
    for (int off = 16; off > 0; off >>= 1)
        v += __shfl_down_sync(0xFFFFFFFFu, v, off);
    if (threadIdx.x == 0)
        out[0] = v * (1.0f / NBATCH);
}

extern "C" void kernel_launch(void* const* d_in, const int* in_sizes, int n_in,
                              void* d_out, int out_size)
{
    const float* snake   = (const float*)d_in[0];
    const float* contour = (const float*)d_in[1];
    float* out = (float*)d_out;

    dtw_kernel<<<NBATCH, TPB>>>(snake, contour);
    reduce_kernel<<<1, 32>>>(out);
}